// round 2
// baseline (speedup 1.0000x reference)
#include <cuda_runtime.h>
#include <cstddef>

#define N_NODES 50000
#define N_EDGES 600000
#define IN_DIM  16
#define HIDDEN  128
#define OUT_DIM 4

// ---------------- device scratch (static: no allocs allowed) ----------------
__device__ int   g_deg[N_NODES];
__device__ int   g_off[N_NODES + 1];
__device__ int   g_pos[N_NODES];
__device__ int   g_csr[N_EDGES];
__device__ int   g_is32;  // 1 if edge_index stored as int32, 0 if int64
__device__ float g_agg[(size_t)N_NODES * HIDDEN];
__device__ float g_h1 [(size_t)N_NODES * HIDDEN];
__device__ float g_h2 [(size_t)N_NODES * HIDDEN];

// ---------------- edge index dtype handling ----------------
__device__ __forceinline__ int load_idx(const void* ei, long long pos, int is32) {
    if (is32) return ((const int*)ei)[pos];
    return (int)(((const long long*)ei)[pos]);
}

// Detect whether edge_index is int32 or int64. If data is int32 but read as
// int64, each value packs two node ids: v = a + (b<<32), which is >= N_NODES
// unless b == 0 (prob ~ (1/N)^64 over 64 samples -> negligible).
__global__ void k_detect(const void* ei) {
    if (threadIdx.x != 0 || blockIdx.x != 0) return;
    const long long* p = (const long long*)ei;
    int is32 = 0;
    for (int i = 0; i < 64; i++) {
        long long v = p[i];
        if (v < 0 || v >= N_NODES) { is32 = 1; break; }
    }
    g_is32 = is32;
}

// ---------------- CSR build ----------------
__global__ void k_zero_deg() {
    int i = blockIdx.x * blockDim.x + threadIdx.x;
    if (i < N_NODES) g_deg[i] = 0;
}

__global__ void k_count(const void* ei) {
    int e = blockIdx.x * blockDim.x + threadIdx.x;
    if (e >= N_EDGES) return;
    int is32 = g_is32;
    int d = load_idx(ei, (long long)N_EDGES + e, is32);
    atomicAdd(&g_deg[d], 1);
}

// single-block exclusive scan of g_deg -> g_off, g_pos
__global__ void k_scan() {
    __shared__ int warp_sums[32];
    __shared__ int s_carry;
    int tid = threadIdx.x;  // 1024 threads
    if (tid == 0) s_carry = 0;
    __syncthreads();
    for (int base = 0; base < N_NODES; base += 1024) {
        int i = base + tid;
        int v = (i < N_NODES) ? g_deg[i] : 0;
        int x = v;
        #pragma unroll
        for (int d = 1; d < 32; d <<= 1) {
            int y = __shfl_up_sync(0xffffffffu, x, d);
            if ((tid & 31) >= d) x += y;
        }
        if ((tid & 31) == 31) warp_sums[tid >> 5] = x;
        __syncthreads();
        if (tid < 32) {
            int w = warp_sums[tid];
            #pragma unroll
            for (int d = 1; d < 32; d <<= 1) {
                int y = __shfl_up_sync(0xffffffffu, w, d);
                if (tid >= d) w += y;
            }
            warp_sums[tid] = w;
        }
        __syncthreads();
        int incl = x + ((tid >= 32) ? warp_sums[(tid >> 5) - 1] : 0);
        int excl = incl - v + s_carry;
        if (i < N_NODES) { g_off[i] = excl; g_pos[i] = excl; }
        int block_total = warp_sums[31];
        __syncthreads();
        if (tid == 0) s_carry += block_total;
        __syncthreads();
    }
    if (tid == 0) g_off[N_NODES] = s_carry;
}

__global__ void k_fill(const void* ei) {
    int e = blockIdx.x * blockDim.x + threadIdx.x;
    if (e >= N_EDGES) return;
    int is32 = g_is32;
    int s = load_idx(ei, e, is32);
    int d = load_idx(ei, (long long)N_EDGES + e, is32);
    int p = atomicAdd(&g_pos[d], 1);
    g_csr[p] = s;
}

// ---------------- aggregation (mean over in-neighbors) ----------------
// F = 16 (layer 1 input): warp per node, lanes 0..15 active.
__global__ void k_agg16(const float* __restrict__ x) {
    int warp = (blockIdx.x * blockDim.x + threadIdx.x) >> 5;
    int lane = threadIdx.x & 31;
    if (warp >= N_NODES) return;
    int beg = g_off[warp], end = g_off[warp + 1];
    float acc = 0.f;
    for (int i = beg; i < end; i++) {
        int s = g_csr[i];
        if (lane < 16) acc += x[(size_t)s * IN_DIM + lane];
    }
    float inv = 1.0f / fmaxf((float)(end - beg), 1.0f);
    if (lane < 16) g_agg[(size_t)warp * IN_DIM + lane] = acc * inv;
}

// F = 128: warp per node, float4 per lane (512B coalesced per neighbor).
__global__ void k_agg128(const float* __restrict__ hin) {
    int warp = (blockIdx.x * blockDim.x + threadIdx.x) >> 5;
    int lane = threadIdx.x & 31;
    if (warp >= N_NODES) return;
    int beg = g_off[warp], end = g_off[warp + 1];
    float4 acc = make_float4(0.f, 0.f, 0.f, 0.f);
    for (int i = beg; i < end; i++) {
        int s = g_csr[i];
        float4 v = *(const float4*)(hin + ((size_t)s << 7) + (lane << 2));
        acc.x += v.x; acc.y += v.y; acc.z += v.z; acc.w += v.w;
    }
    float inv = 1.0f / fmaxf((float)(end - beg), 1.0f);
    float4 r = make_float4(acc.x * inv, acc.y * inv, acc.z * inv, acc.w * inv);
    *(float4*)(g_agg + ((size_t)warp << 7) + (lane << 2)) = r;
}

// ---------------- fused SAGE linear: out = act(A1@W1^T + A2@W2^T + b) -------
// A1, A2: [M, K] row-major.  W1, W2: [128, K] row-major.  out: [M, 128].
// Tile: BM=128, BN=128, BK=16. 256 threads, 8x8 microtile per thread.
__global__ __launch_bounds__(256)
void k_sage_gemm(const float* __restrict__ A1, const float* __restrict__ A2,
                 const float* __restrict__ W1, const float* __restrict__ W2,
                 const float* __restrict__ bias, float* __restrict__ out,
                 int K, int do_relu)
{
    __shared__ float As[16][128];
    __shared__ float Ws[16][128];
    int tid = threadIdx.x;
    int tx = tid & 15;   // n dim (x8)
    int ty = tid >> 4;   // m dim (x8)
    int row0 = blockIdx.x * 128;

    float c[8][8];
    #pragma unroll
    for (int i = 0; i < 8; i++)
        #pragma unroll
        for (int j = 0; j < 8; j++) c[i][j] = 0.f;

    #pragma unroll
    for (int seg = 0; seg < 2; seg++) {
        const float* A = seg ? A2 : A1;
        const float* W = seg ? W2 : W1;
        for (int kk = 0; kk < K; kk += 16) {
            // load tiles: 512 float4 each for A and W; 2 float4/thread each
            #pragma unroll
            for (int t = 0; t < 2; t++) {
                int idx = tid + t * 256;   // 0..511
                int m  = idx >> 2;         // 0..127
                int kq = idx & 3;          // float4 within 16-wide k chunk
                int gm = row0 + m;
                float4 v = make_float4(0.f, 0.f, 0.f, 0.f);
                if (gm < N_NODES)
                    v = *(const float4*)(A + (size_t)gm * K + kk + kq * 4);
                As[kq * 4 + 0][m] = v.x;
                As[kq * 4 + 1][m] = v.y;
                As[kq * 4 + 2][m] = v.z;
                As[kq * 4 + 3][m] = v.w;
                float4 w = *(const float4*)(W + (size_t)m * K + kk + kq * 4);
                Ws[kq * 4 + 0][m] = w.x;
                Ws[kq * 4 + 1][m] = w.y;
                Ws[kq * 4 + 2][m] = w.z;
                Ws[kq * 4 + 3][m] = w.w;
            }
            __syncthreads();
            #pragma unroll
            for (int k = 0; k < 16; k++) {
                float a[8], w[8];
                *(float4*)&a[0] = *(const float4*)&As[k][ty * 8];
                *(float4*)&a[4] = *(const float4*)&As[k][ty * 8 + 4];
                *(float4*)&w[0] = *(const float4*)&Ws[k][tx * 8];
                *(float4*)&w[4] = *(const float4*)&Ws[k][tx * 8 + 4];
                #pragma unroll
                for (int i = 0; i < 8; i++)
                    #pragma unroll
                    for (int j = 0; j < 8; j++)
                        c[i][j] += a[i] * w[j];
            }
            __syncthreads();
        }
    }

    #pragma unroll
    for (int i = 0; i < 8; i++) {
        int gm = row0 + ty * 8 + i;
        if (gm >= N_NODES) continue;
        #pragma unroll
        for (int j = 0; j < 8; j += 4) {
            int gn = tx * 8 + j;
            float4 v;
            v.x = c[i][j + 0] + bias[gn + 0];
            v.y = c[i][j + 1] + bias[gn + 1];
            v.z = c[i][j + 2] + bias[gn + 2];
            v.w = c[i][j + 3] + bias[gn + 3];
            if (do_relu) {
                v.x = fmaxf(v.x, 0.f); v.y = fmaxf(v.y, 0.f);
                v.z = fmaxf(v.z, 0.f); v.w = fmaxf(v.w, 0.f);
            }
            *(float4*)(out + (size_t)gm * 128 + gn) = v;
        }
    }
}

// ---------------- head: out = h @ Wh^T + bh (OUT_DIM=4) ----------------
__global__ void k_head(const float* __restrict__ h, const float* __restrict__ Wh,
                       const float* __restrict__ bh, float* __restrict__ out)
{
    int warp = (blockIdx.x * blockDim.x + threadIdx.x) >> 5;
    int lane = threadIdx.x & 31;
    if (warp >= N_NODES) return;
    float4 hv = *(const float4*)(h + ((size_t)warp << 7) + (lane << 2));
    float p[4];
    #pragma unroll
    for (int o = 0; o < 4; o++) {
        float4 w = *(const float4*)(Wh + o * 128 + (lane << 2));
        float s = hv.x * w.x + hv.y * w.y + hv.z * w.z + hv.w * w.w;
        #pragma unroll
        for (int d = 16; d > 0; d >>= 1) s += __shfl_xor_sync(0xffffffffu, s, d);
        p[o] = s;
    }
    if (lane == 0) {
        float4 v = make_float4(p[0] + bh[0], p[1] + bh[1], p[2] + bh[2], p[3] + bh[3]);
        *(float4*)(out + (size_t)warp * 4) = v;
    }
}

// ---------------- launch ----------------
extern "C" void kernel_launch(void* const* d_in, const int* in_sizes, int n_in,
                              void* d_out, int out_size)
{
    const float* x   = (const float*)d_in[0];
    const void*  ei  = d_in[1];
    const float* Wl1 = (const float*)d_in[2];
    const float* Wr1 = (const float*)d_in[3];
    const float* b1  = (const float*)d_in[4];
    const float* Wl2 = (const float*)d_in[5];
    const float* Wr2 = (const float*)d_in[6];
    const float* b2  = (const float*)d_in[7];
    const float* Wl3 = (const float*)d_in[8];
    const float* Wr3 = (const float*)d_in[9];
    const float* b3  = (const float*)d_in[10];
    const float* Wh  = (const float*)d_in[11];
    const float* bh  = (const float*)d_in[12];
    float* out = (float*)d_out;

    float *p_agg, *p_h1, *p_h2;
    cudaGetSymbolAddress((void**)&p_agg, g_agg);
    cudaGetSymbolAddress((void**)&p_h1,  g_h1);
    cudaGetSymbolAddress((void**)&p_h2,  g_h2);

    const int EB = (N_EDGES + 255) / 256;
    const int NB = (N_NODES + 255) / 256;
    const int WB = (N_NODES + 7) / 8;          // warp-per-node kernels, 256 thr
    const int GB = (N_NODES + 127) / 128;      // gemm blocks

    k_detect<<<1, 32>>>(ei);
    k_zero_deg<<<NB, 256>>>();
    k_count<<<EB, 256>>>(ei);
    k_scan<<<1, 1024>>>();
    k_fill<<<EB, 256>>>(ei);

    // layer 1: agg(x) [N,16]; h1 = relu(agg@Wl1^T + x@Wr1^T + b1)
    k_agg16<<<WB, 256>>>(x);
    k_sage_gemm<<<GB, 256>>>(p_agg, x, Wl1, Wr1, b1, p_h1, IN_DIM, 1);

    // layer 2
    k_agg128<<<WB, 256>>>(p_h1);
    k_sage_gemm<<<GB, 256>>>(p_agg, p_h1, Wl2, Wr2, b2, p_h2, HIDDEN, 1);

    // layer 3
    k_agg128<<<WB, 256>>>(p_h2);
    k_sage_gemm<<<GB, 256>>>(p_agg, p_h2, Wl3, Wr3, b3, p_h1, HIDDEN, 1);

    // head
    k_head<<<WB, 256>>>(p_h1, Wh, bh, out);
}

// round 4
// speedup vs baseline: 1.5713x; 1.5713x over previous
#include <cuda_runtime.h>
#include <cuda_bf16.h>
#include <cstdint>
#include <cstddef>

#define N_NODES 50000
#define N_EDGES 600000
#define IN_DIM  16
#define HIDDEN  128
#define OUT_DIM 4

typedef __nv_bfloat16 bf16;

// ---------------- device scratch (static: no allocs allowed) ----------------
__device__ int   g_deg[N_NODES];
__device__ int   g_off[N_NODES + 1];
__device__ int   g_pos[N_NODES];
__device__ int   g_csr[N_EDGES];
__device__ int   g_is32;
__device__ int   g_bsum[80];

__device__ float g_agg[(size_t)N_NODES * IN_DIM];      // layer1 agg (f32)
__device__ float g_h1 [(size_t)N_NODES * HIDDEN];      // f32 activations
__device__ float g_h2 [(size_t)N_NODES * HIDDEN];
// bf16 hi/lo splits
__device__ bf16  g_aggh[(size_t)N_NODES * HIDDEN];
__device__ bf16  g_aggl[(size_t)N_NODES * HIDDEN];
__device__ bf16  g_h1h [(size_t)N_NODES * HIDDEN];
__device__ bf16  g_h1l [(size_t)N_NODES * HIDDEN];
__device__ bf16  g_h2h [(size_t)N_NODES * HIDDEN];
__device__ bf16  g_h2l [(size_t)N_NODES * HIDDEN];
// W splits: order Wl2, Wr2, Wl3, Wr3
__device__ bf16  g_Wh[4][HIDDEN * HIDDEN];
__device__ bf16  g_Wl[4][HIDDEN * HIDDEN];

// ---------------- helpers ----------------
__device__ __forceinline__ void bsplit(float x, bf16& h, bf16& l) {
    h = __float2bfloat16_rn(x);
    l = __float2bfloat16_rn(x - __bfloat162float(h));
}

__device__ __forceinline__ void mma_bf16(float c[4], const uint32_t a[4],
                                         uint32_t b0, uint32_t b1) {
    asm volatile(
        "mma.sync.aligned.m16n8k16.row.col.f32.bf16.bf16.f32 "
        "{%0,%1,%2,%3}, {%4,%5,%6,%7}, {%8,%9}, {%0,%1,%2,%3};"
        : "+f"(c[0]), "+f"(c[1]), "+f"(c[2]), "+f"(c[3])
        : "r"(a[0]), "r"(a[1]), "r"(a[2]), "r"(a[3]), "r"(b0), "r"(b1));
}

// ---------------- edge index dtype handling ----------------
__device__ __forceinline__ int load_idx(const void* ei, long long pos, int is32) {
    if (is32) return ((const int*)ei)[pos];
    return (int)(((const long long*)ei)[pos]);
}

__global__ void k_detect(const void* ei) {
    int t = threadIdx.x;  // 64 threads
    const long long* p = (const long long*)ei;
    long long v = p[t];
    int bad = (v < 0 || v >= N_NODES) ? 1 : 0;
    unsigned m0 = __ballot_sync(0xffffffffu, bad);
    __shared__ unsigned s_m[2];
    s_m[t >> 5] = m0;
    __syncthreads();
    if (t == 0) g_is32 = (s_m[0] | s_m[1]) ? 1 : 0;
}

// ---------------- CSR build ----------------
__global__ void k_zero_deg() {
    int i = blockIdx.x * blockDim.x + threadIdx.x;
    if (i < N_NODES) g_deg[i] = 0;
}

__global__ void k_count(const void* ei) {
    int e = blockIdx.x * blockDim.x + threadIdx.x;
    if (e >= N_EDGES) return;
    int is32 = g_is32;
    int d = load_idx(ei, (long long)N_EDGES + e, is32);
    atomicAdd(&g_deg[d], 1);
}

// pass 1: per-block exclusive scan + block sums
__global__ void k_scan1() {
    __shared__ int warp_sums[32];
    int tid = threadIdx.x;  // 1024
    int i = blockIdx.x * 1024 + tid;
    int v = (i < N_NODES) ? g_deg[i] : 0;
    int x = v;
    #pragma unroll
    for (int d = 1; d < 32; d <<= 1) {
        int y = __shfl_up_sync(0xffffffffu, x, d);
        if ((tid & 31) >= d) x += y;
    }
    if ((tid & 31) == 31) warp_sums[tid >> 5] = x;
    __syncthreads();
    if (tid < 32) {
        int w = warp_sums[tid];
        #pragma unroll
        for (int d = 1; d < 32; d <<= 1) {
            int y = __shfl_up_sync(0xffffffffu, w, d);
            if (tid >= d) w += y;
        }
        warp_sums[tid] = w;
    }
    __syncthreads();
    int incl = x + ((tid >= 32) ? warp_sums[(tid >> 5) - 1] : 0);
    if (i < N_NODES) g_off[i] = incl - v;
    if (tid == 0) g_bsum[blockIdx.x] = warp_sums[31];
}

// pass 2: scan the block sums (1 warp, covers up to 64 blocks)
__global__ void k_scan2(int nblk) {
    int t = threadIdx.x;  // 32
    int v0 = (t < nblk) ? g_bsum[t] : 0;
    int v1 = (32 + t < nblk) ? g_bsum[32 + t] : 0;
    int x0 = v0, x1 = v1;
    #pragma unroll
    for (int d = 1; d < 32; d <<= 1) {
        int y0 = __shfl_up_sync(0xffffffffu, x0, d);
        int y1 = __shfl_up_sync(0xffffffffu, x1, d);
        if (t >= d) { x0 += y0; x1 += y1; }
    }
    int tot0 = __shfl_sync(0xffffffffu, x0, 31);
    int tot1 = __shfl_sync(0xffffffffu, x1, 31);
    g_bsum[t] = x0 - v0;
    g_bsum[32 + t] = x1 - v1 + tot0;
    if (t == 0) g_off[N_NODES] = tot0 + tot1;
}

// pass 3: add block offsets
__global__ void k_scan3() {
    int i = blockIdx.x * 1024 + threadIdx.x;
    if (i >= N_NODES) return;
    int off = g_off[i] + g_bsum[blockIdx.x];
    g_off[i] = off;
    g_pos[i] = off;
}

__global__ void k_fill(const void* ei) {
    int e = blockIdx.x * blockDim.x + threadIdx.x;
    if (e >= N_EDGES) return;
    int is32 = g_is32;
    int s = load_idx(ei, e, is32);
    int d = load_idx(ei, (long long)N_EDGES + e, is32);
    int p = atomicAdd(&g_pos[d], 1);
    g_csr[p] = s;
}

// ---------------- W pre-split (bf16 hi/lo) ----------------
__global__ void k_splitW(const float* __restrict__ Wl2, const float* __restrict__ Wr2,
                         const float* __restrict__ Wl3, const float* __restrict__ Wr3) {
    int idx = blockIdx.x * blockDim.x + threadIdx.x;  // 64 * 1024 = 65536
    int w = idx >> 14;
    int e = idx & 16383;
    const float* src = (w == 0) ? Wl2 : (w == 1) ? Wr2 : (w == 2) ? Wl3 : Wr3;
    float v = src[e];
    bf16 h, l;
    bsplit(v, h, l);
    g_Wh[w][e] = h;
    g_Wl[w][e] = l;
}

// ---------------- aggregation ----------------
__global__ void k_agg16(const float* __restrict__ x) {
    int warp = (blockIdx.x * blockDim.x + threadIdx.x) >> 5;
    int lane = threadIdx.x & 31;
    if (warp >= N_NODES) return;
    int beg = g_off[warp], end = g_off[warp + 1];
    float acc = 0.f;
    for (int i = beg; i < end; i++) {
        int s = g_csr[i];
        if (lane < 16) acc += x[(size_t)s * IN_DIM + lane];
    }
    float inv = 1.0f / fmaxf((float)(end - beg), 1.0f);
    if (lane < 16) g_agg[(size_t)warp * IN_DIM + lane] = acc * inv;
}

// F=128 mean agg (f32 in) -> bf16 hi/lo out
__global__ void k_agg128(const float* __restrict__ hin,
                         bf16* __restrict__ oh, bf16* __restrict__ ol) {
    int warp = (blockIdx.x * blockDim.x + threadIdx.x) >> 5;
    int lane = threadIdx.x & 31;
    if (warp >= N_NODES) return;
    int beg = g_off[warp], end = g_off[warp + 1];
    float4 acc = make_float4(0.f, 0.f, 0.f, 0.f);
    for (int i = beg; i < end; i++) {
        int s = g_csr[i];
        float4 v = *(const float4*)(hin + ((size_t)s << 7) + (lane << 2));
        acc.x += v.x; acc.y += v.y; acc.z += v.z; acc.w += v.w;
    }
    float inv = 1.0f / fmaxf((float)(end - beg), 1.0f);
    float r[4] = {acc.x * inv, acc.y * inv, acc.z * inv, acc.w * inv};
    bf16 rh[4], rl[4];
    #pragma unroll
    for (int j = 0; j < 4; j++) bsplit(r[j], rh[j], rl[j]);
    size_t o = ((size_t)warp << 7) + (lane << 2);
    *(uint2*)(oh + o) = *(const uint2*)rh;
    *(uint2*)(ol + o) = *(const uint2*)rl;
}

// ---------------- layer-1 FFMA GEMM (K=16 per segment) ----------------
__global__ __launch_bounds__(256)
void k_sage_gemm(const float* __restrict__ A1, const float* __restrict__ A2,
                 const float* __restrict__ W1, const float* __restrict__ W2,
                 const float* __restrict__ bias, float* __restrict__ out,
                 bf16* __restrict__ out_hi, bf16* __restrict__ out_lo,
                 int K)
{
    __shared__ float As[16][128];
    __shared__ float Ws[16][128];
    int tid = threadIdx.x;
    int tx = tid & 15;
    int ty = tid >> 4;
    int row0 = blockIdx.x * 128;

    float c[8][8];
    #pragma unroll
    for (int i = 0; i < 8; i++)
        #pragma unroll
        for (int j = 0; j < 8; j++) c[i][j] = 0.f;

    #pragma unroll
    for (int seg = 0; seg < 2; seg++) {
        const float* A = seg ? A2 : A1;
        const float* W = seg ? W2 : W1;
        for (int kk = 0; kk < K; kk += 16) {
            #pragma unroll
            for (int t = 0; t < 2; t++) {
                int idx = tid + t * 256;
                int m  = idx >> 2;
                int kq = idx & 3;
                int gm = row0 + m;
                float4 v = make_float4(0.f, 0.f, 0.f, 0.f);
                if (gm < N_NODES)
                    v = *(const float4*)(A + (size_t)gm * K + kk + kq * 4);
                As[kq * 4 + 0][m] = v.x; As[kq * 4 + 1][m] = v.y;
                As[kq * 4 + 2][m] = v.z; As[kq * 4 + 3][m] = v.w;
                float4 w = *(const float4*)(W + (size_t)m * K + kk + kq * 4);
                Ws[kq * 4 + 0][m] = w.x; Ws[kq * 4 + 1][m] = w.y;
                Ws[kq * 4 + 2][m] = w.z; Ws[kq * 4 + 3][m] = w.w;
            }
            __syncthreads();
            #pragma unroll
            for (int k = 0; k < 16; k++) {
                float a[8], w[8];
                *(float4*)&a[0] = *(const float4*)&As[k][ty * 8];
                *(float4*)&a[4] = *(const float4*)&As[k][ty * 8 + 4];
                *(float4*)&w[0] = *(const float4*)&Ws[k][tx * 8];
                *(float4*)&w[4] = *(const float4*)&Ws[k][tx * 8 + 4];
                #pragma unroll
                for (int i = 0; i < 8; i++)
                    #pragma unroll
                    for (int j = 0; j < 8; j++)
                        c[i][j] += a[i] * w[j];
            }
            __syncthreads();
        }
    }

    #pragma unroll
    for (int i = 0; i < 8; i++) {
        int gm = row0 + ty * 8 + i;
        if (gm >= N_NODES) continue;
        #pragma unroll
        for (int j = 0; j < 8; j += 4) {
            int gn = tx * 8 + j;
            float v[4];
            #pragma unroll
            for (int q = 0; q < 4; q++)
                v[q] = fmaxf(c[i][j + q] + bias[gn + q], 0.f);
            *(float4*)(out + (size_t)gm * 128 + gn) = *(const float4*)v;
            bf16 vh[4], vl[4];
            #pragma unroll
            for (int q = 0; q < 4; q++) bsplit(v[q], vh[q], vl[q]);
            *(uint2*)(out_hi + (size_t)gm * 128 + gn) = *(const uint2*)vh;
            *(uint2*)(out_lo + (size_t)gm * 128 + gn) = *(const uint2*)vl;
        }
    }
}

// ---------------- bf16 split-HMMA GEMM (layers 2+3) ----------------
// out[M,128] = relu([A1|A2](M,256) @ [B1|B2](128,256)^T + bias)
// A, B given as bf16 hi/lo. 3-term split: hi*hi + hi*lo + lo*hi.
// CTA: 128x128 tile, 256 thr = 8 warps (4 m x 2 n). warp: 32x64.
// mma.m16n8k16: per warp 2 m-tiles x 8 n-tiles.
#define SK 40   // smem row stride in halves (conflict-free fragment loads)

__global__ __launch_bounds__(256, 2)
void k_mma_gemm(const bf16* __restrict__ A1h, const bf16* __restrict__ A1l,
                const bf16* __restrict__ A2h, const bf16* __restrict__ A2l,
                const bf16* __restrict__ B1h, const bf16* __restrict__ B1l,
                const bf16* __restrict__ B2h, const bf16* __restrict__ B2l,
                const float* __restrict__ bias, float* __restrict__ out,
                bf16* __restrict__ out_hi, bf16* __restrict__ out_lo,
                int write_hilo)
{
    __shared__ bf16 sAh[128][SK], sAl[128][SK], sWh[128][SK], sWl[128][SK];
    int tid = threadIdx.x;
    int wid = tid >> 5;
    int lane = tid & 31;
    int tg = lane & 3;        // thread-in-group
    int gp = lane >> 2;       // group id 0..7
    int warp_m = wid & 3;     // 4 tiles of 32 rows
    int warp_n = wid >> 2;    // 2 tiles of 64 cols
    int row0 = blockIdx.x * 128;

    float c[2][8][4];
    #pragma unroll
    for (int mt = 0; mt < 2; mt++)
        #pragma unroll
        for (int nt = 0; nt < 8; nt++)
            #pragma unroll
            for (int q = 0; q < 4; q++) c[mt][nt][q] = 0.f;

    for (int ch = 0; ch < 8; ch++) {
        int seg = ch >> 2;
        int k0 = (ch & 3) * 32;
        const bf16* Ah = seg ? A2h : A1h;
        const bf16* Al = seg ? A2l : A1l;
        const bf16* Bh = seg ? B2h : B1h;
        const bf16* Bl = seg ? B2l : B1l;

        if (ch) __syncthreads();
        // load 128x32 bf16 tiles: 2 float4 (=8 bf16) per thread per buffer
        #pragma unroll
        for (int t = 0; t < 2; t++) {
            int idx = tid + t * 256;   // 0..511
            int m = idx >> 2;          // 0..127
            int q = idx & 3;           // 8-half group within 32
            int gm = row0 + m;
            float4 va = make_float4(0.f, 0.f, 0.f, 0.f), vb = va;
            if (gm < N_NODES) {
                va = *(const float4*)(Ah + (size_t)gm * 128 + k0 + q * 8);
                vb = *(const float4*)(Al + (size_t)gm * 128 + k0 + q * 8);
            }
            *(float4*)&sAh[m][q * 8] = va;
            *(float4*)&sAl[m][q * 8] = vb;
            float4 wh = *(const float4*)(Bh + (size_t)m * 128 + k0 + q * 8);
            float4 wl = *(const float4*)(Bl + (size_t)m * 128 + k0 + q * 8);
            *(float4*)&sWh[m][q * 8] = wh;
            *(float4*)&sWl[m][q * 8] = wl;
        }
        __syncthreads();

        #pragma unroll
        for (int ks = 0; ks < 2; ks++) {
            int kh = ks * 16;
            uint32_t ah[2][4], al[2][4];
            #pragma unroll
            for (int mt = 0; mt < 2; mt++) {
                int r = warp_m * 32 + mt * 16 + gp;
                ah[mt][0] = *(const uint32_t*)&sAh[r    ][kh + 2 * tg];
                ah[mt][1] = *(const uint32_t*)&sAh[r + 8][kh + 2 * tg];
                ah[mt][2] = *(const uint32_t*)&sAh[r    ][kh + 8 + 2 * tg];
                ah[mt][3] = *(const uint32_t*)&sAh[r + 8][kh + 8 + 2 * tg];
                al[mt][0] = *(const uint32_t*)&sAl[r    ][kh + 2 * tg];
                al[mt][1] = *(const uint32_t*)&sAl[r + 8][kh + 2 * tg];
                al[mt][2] = *(const uint32_t*)&sAl[r    ][kh + 8 + 2 * tg];
                al[mt][3] = *(const uint32_t*)&sAl[r + 8][kh + 8 + 2 * tg];
            }
            #pragma unroll
            for (int nt = 0; nt < 8; nt++) {
                int n = warp_n * 64 + nt * 8 + gp;
                uint32_t bh0 = *(const uint32_t*)&sWh[n][kh + 2 * tg];
                uint32_t bh1 = *(const uint32_t*)&sWh[n][kh + 8 + 2 * tg];
                uint32_t bl0 = *(const uint32_t*)&sWl[n][kh + 2 * tg];
                uint32_t bl1 = *(const uint32_t*)&sWl[n][kh + 8 + 2 * tg];
                #pragma unroll
                for (int mt = 0; mt < 2; mt++) {
                    mma_bf16(c[mt][nt], ah[mt], bh0, bh1);
                    mma_bf16(c[mt][nt], ah[mt], bl0, bl1);
                    mma_bf16(c[mt][nt], al[mt], bh0, bh1);
                }
            }
        }
    }

    // epilogue: c0,c1 -> (row, col..col+1); c2,c3 -> (row+8, ...)
    #pragma unroll
    for (int mt = 0; mt < 2; mt++) {
        int row = row0 + warp_m * 32 + mt * 16 + gp;
        #pragma unroll
        for (int nt = 0; nt < 8; nt++) {
            int col = warp_n * 64 + nt * 8 + 2 * tg;
            float b0 = bias[col], b1 = bias[col + 1];
            if (row < N_NODES) {
                float v0 = fmaxf(c[mt][nt][0] + b0, 0.f);
                float v1 = fmaxf(c[mt][nt][1] + b1, 0.f);
                *(float2*)(out + (size_t)row * 128 + col) = make_float2(v0, v1);
                if (write_hilo) {
                    bf16 h0, l0, h1, l1;
                    bsplit(v0, h0, l0); bsplit(v1, h1, l1);
                    bf16 hh[2] = {h0, h1}, ll[2] = {l0, l1};
                    *(uint32_t*)(out_hi + (size_t)row * 128 + col) = *(const uint32_t*)hh;
                    *(uint32_t*)(out_lo + (size_t)row * 128 + col) = *(const uint32_t*)ll;
                }
            }
            int row2 = row + 8;
            if (row2 < N_NODES) {
                float v2 = fmaxf(c[mt][nt][2] + b0, 0.f);
                float v3 = fmaxf(c[mt][nt][3] + b1, 0.f);
                *(float2*)(out + (size_t)row2 * 128 + col) = make_float2(v2, v3);
                if (write_hilo) {
                    bf16 h2, l2, h3, l3;
                    bsplit(v2, h2, l2); bsplit(v3, h3, l3);
                    bf16 hh[2] = {h2, h3}, ll[2] = {l2, l3};
                    *(uint32_t*)(out_hi + (size_t)row2 * 128 + col) = *(const uint32_t*)hh;
                    *(uint32_t*)(out_lo + (size_t)row2 * 128 + col) = *(const uint32_t*)ll;
                }
            }
        }
    }
}

// ---------------- head ----------------
__global__ void k_head(const float* __restrict__ h, const float* __restrict__ Wh,
                       const float* __restrict__ bh, float* __restrict__ out)
{
    int warp = (blockIdx.x * blockDim.x + threadIdx.x) >> 5;
    int lane = threadIdx.x & 31;
    if (warp >= N_NODES) return;
    float4 hv = *(const float4*)(h + ((size_t)warp << 7) + (lane << 2));
    float p[4];
    #pragma unroll
    for (int o = 0; o < 4; o++) {
        float4 w = *(const float4*)(Wh + o * 128 + (lane << 2));
        float s = hv.x * w.x + hv.y * w.y + hv.z * w.z + hv.w * w.w;
        #pragma unroll
        for (int d = 16; d > 0; d >>= 1) s += __shfl_xor_sync(0xffffffffu, s, d);
        p[o] = s;
    }
    if (lane == 0) {
        float4 v = make_float4(p[0] + bh[0], p[1] + bh[1], p[2] + bh[2], p[3] + bh[3]);
        *(float4*)(out + (size_t)warp * 4) = v;
    }
}

// ---------------- launch ----------------
extern "C" void kernel_launch(void* const* d_in, const int* in_sizes, int n_in,
                              void* d_out, int out_size)
{
    const float* x   = (const float*)d_in[0];
    const void*  ei  = d_in[1];
    const float* Wl1 = (const float*)d_in[2];
    const float* Wr1 = (const float*)d_in[3];
    const float* b1  = (const float*)d_in[4];
    const float* Wl2 = (const float*)d_in[5];
    const float* Wr2 = (const float*)d_in[6];
    const float* b2  = (const float*)d_in[7];
    const float* Wl3 = (const float*)d_in[8];
    const float* Wr3 = (const float*)d_in[9];
    const float* b3  = (const float*)d_in[10];
    const float* Wh  = (const float*)d_in[11];
    const float* bh  = (const float*)d_in[12];
    float* out = (float*)d_out;

    float *p_agg, *p_h1, *p_h2;
    bf16 *p_aggh, *p_aggl, *p_h1h, *p_h1l, *p_h2h, *p_h2l, *p_Whs, *p_Wls;
    cudaGetSymbolAddress((void**)&p_agg,  g_agg);
    cudaGetSymbolAddress((void**)&p_h1,   g_h1);
    cudaGetSymbolAddress((void**)&p_h2,   g_h2);
    cudaGetSymbolAddress((void**)&p_aggh, g_aggh);
    cudaGetSymbolAddress((void**)&p_aggl, g_aggl);
    cudaGetSymbolAddress((void**)&p_h1h,  g_h1h);
    cudaGetSymbolAddress((void**)&p_h1l,  g_h1l);
    cudaGetSymbolAddress((void**)&p_h2h,  g_h2h);
    cudaGetSymbolAddress((void**)&p_h2l,  g_h2l);
    cudaGetSymbolAddress((void**)&p_Whs,  g_Wh);
    cudaGetSymbolAddress((void**)&p_Wls,  g_Wl);

    const int EB = (N_EDGES + 255) / 256;
    const int NB = (N_NODES + 255) / 256;
    const int WB = (N_NODES + 7) / 8;
    const int GB = (N_NODES + 127) / 128;
    const int SB = (N_NODES + 1023) / 1024;  // 49

    // graph structure + W split
    k_detect<<<1, 64>>>(ei);
    k_splitW<<<64, 1024>>>(Wl2, Wr2, Wl3, Wr3);
    k_zero_deg<<<NB, 256>>>();
    k_count<<<EB, 256>>>(ei);
    k_scan1<<<SB, 1024>>>();
    k_scan2<<<1, 32>>>(SB);
    k_scan3<<<SB, 1024>>>();
    k_fill<<<EB, 256>>>(ei);

    const int HH = HIDDEN * HIDDEN;

    // layer 1 (FFMA, K=16)
    k_agg16<<<WB, 256>>>(x);
    k_sage_gemm<<<GB, 256>>>(p_agg, x, Wl1, Wr1, b1, p_h1, p_h1h, p_h1l, IN_DIM);

    // layer 2 (bf16 split HMMA)
    k_agg128<<<WB, 256>>>(p_h1, p_aggh, p_aggl);
    k_mma_gemm<<<GB, 256>>>(p_aggh, p_aggl, p_h1h, p_h1l,
                            p_Whs + 0 * HH, p_Wls + 0 * HH,
                            p_Whs + 1 * HH, p_Wls + 1 * HH,
                            b2, p_h2, p_h2h, p_h2l, 1);

    // layer 3 (bf16 split HMMA)
    k_agg128<<<WB, 256>>>(p_h2, p_aggh, p_aggl);
    k_mma_gemm<<<GB, 256>>>(p_aggh, p_aggl, p_h2h, p_h2l,
                            p_Whs + 2 * HH, p_Wls + 2 * HH,
                            p_Whs + 3 * HH, p_Wls + 3 * HH,
                            b3, p_h1, p_h1h, p_h1l, 0);

    // head
    k_head<<<WB, 256>>>(p_h1, Wh, bh, out);
}